// round 8
// baseline (speedup 1.0000x reference)
#include <cuda_runtime.h>

// Problem constants
#define B_   32
#define H_   56
#define W_   56
#define C_   256

// Conv tiling: 64 channels/block, 2 rowteams x 4 col-teams x 32 channel-pairs
#define BDIM   256
#define CQTR   64        // channels per block
#define NGRP   8         // groups per block
#define ROWW   60        // padded smem row length (56 + halo + align, mult of 4)
#define CHPAD  (NGRP * 9)                    // 72, stride-9 padding
#define SLOT   (CHPAD * ROWW)                // 4320 floats per row-slot
#define NSLOT  6                             // ring: reads r-1..r+2, writes r+3,r+4
#define SMEM_FLOATS (NSLOT * SLOT)           // 25920
#define SMEM_BYTES  (SMEM_FLOATS * 4)        // 103680 -> 2 blocks/SM
#define RPB    8         // output rows per block (2 rows x 4 steps)

#define NPART  1792      // 7 rowblocks * 32 n * 4 teams * 2 rowteams

__device__ float g_psum  [C_ * NPART];
__device__ float g_psumsq[C_ * NPART];
__device__ float g_scale[C_];
__device__ float g_shift[C_];

// Pre-broadcast weights: g_wb[k*128 + c/2] = ulonglong2{ (w[k][c],w[k][c]),
// (w[k][c+1],w[k][c+1]) } -- one LDG.128 delivers both channels' broadcast
// pairs for a tap, zero pack MOVs in the hot loop.
__device__ ulonglong2 g_wb[72 * 128];

typedef unsigned long long u64;

__device__ __forceinline__ u64 fma2(u64 a, u64 b, u64 c) {
    u64 d; asm("fma.rn.f32x2 %0, %1, %2, %3;" : "=l"(d) : "l"(a), "l"(b), "l"(c)); return d;
}
__device__ __forceinline__ float u2lo(u64 v) { return __uint_as_float((unsigned)v); }
__device__ __forceinline__ float u2hi(u64 v) { return __uint_as_float((unsigned)(v >> 32)); }

__device__ __forceinline__ int slot_of(int row) { return (row + 6) % 6; }

// LDG.128 -> 4x STS.32 load of one input row into its ring slot.
__device__ __forceinline__ void load_row(float* smem, const float* __restrict__ x,
                                         int n, int hh, int cbase, int t)
{
    float* slot = smem + (size_t)slot_of(hh) * SLOT;
    const float4* src = (const float4*)(x + ((size_t)(n * H_ + hh) * W_) * C_ + cbase);
    #pragma unroll
    for (int it = 0; it < 4; it++) {
        const int f = t + it * BDIM;
        if (f < 56 * 16) {
            const int col = f >> 4;
            const int c4  = f & 15;
            const float4 v = __ldg(&src[col * (C_ / 4) + c4]);
            const int g    = c4 >> 1;
            const int ioff = (c4 & 1) * 4;
            float* dst = slot + (size_t)(g * 9 + ioff) * ROWW + (col + 1);
            dst[0 * ROWW] = v.x;  dst[1 * ROWW] = v.y;
            dst[2 * ROWW] = v.z;  dst[3 * ROWW] = v.w;
        }
    }
}

__device__ __forceinline__ void zero_row(float* smem, int hh, int t)
{
    float* slot = smem + (size_t)slot_of(hh) * SLOT;
    #pragma unroll
    for (int it = 0; it < 4; it++) {
        const int f = t + it * BDIM;
        if (f < 56 * 16) {
            const int col = f >> 4;
            const int c4  = f & 15;
            const int g    = c4 >> 1;
            const int ioff = (c4 & 1) * 4;
            float* dst = slot + (size_t)(g * 9 + ioff) * ROWW + (col + 1);
            dst[0 * ROWW] = 0.f;  dst[1 * ROWW] = 0.f;
            dst[2 * ROWW] = 0.f;  dst[3 * ROWW] = 0.f;
        }
    }
}

// ---------------------------------------------------------------------------
// Kernel 0: pre-broadcast the weights (72*128 ulonglong2 entries)
// ---------------------------------------------------------------------------
__global__ void wpack_kernel(const float* __restrict__ w)
{
    const int idx = blockIdx.x * 256 + threadIdx.x;   // 0 .. 72*128-1
    if (idx >= 72 * 128) return;
    const int k  = idx >> 7;
    const int c2 = idx & 127;
    const float wA = w[k * C_ + 2 * c2];
    const float wB = w[k * C_ + 2 * c2 + 1];
    float2* f2 = (float2*)&g_wb[idx];
    f2[0] = make_float2(wA, wA);
    f2[1] = make_float2(wB, wB);
}

// ---------------------------------------------------------------------------
// Kernel 1: grouped conv. Per thread: channel pair (A,B) x 14 cols, all-f32x2.
// Aligned input pairs PR[q]=(x[cb+2q-1], x[cb+2q]) feed kw0 (main acc), kw2
// (main acc, shifted index) and kw1 (shifted-mid accumulators) with ZERO pack
// MOVs; weights arrive pre-broadcast via one LDG.128 per tap.
// grid = (7, 32, 4); block = 256. Bias omitted (cancelled by BN mean-sub).
// ---------------------------------------------------------------------------
__global__ __launch_bounds__(BDIM, 2)
void conv_kernel(const float* __restrict__ x, float* __restrict__ y)
{
    extern __shared__ float smem[];
    const int t       = threadIdx.x;
    const int rowteam = t >> 7;            // 0/1
    const int tt      = t & 127;
    const int team    = tt >> 5;           // col team 0..3
    const int ps      = tt & 31;           // channel-pair slot
    const int gl      = ps >> 2;           // local group 0..7
    const int bx      = blockIdx.x;        // 0..6
    const int n       = blockIdx.y;
    const int z       = blockIdx.z;        // 0..3
    const int cbase   = z * CQTR;
    const int o0      = cbase + 2 * ps;    // first of channel pair (even)
    const int h0      = bx * RPB;
    const int cb      = team * 14;         // first output col (even)

    // Zero smem ring (halo cols + virtual OOB rows)
    {
        float4* s4 = (float4*)smem;
        const float4 z4 = make_float4(0.f, 0.f, 0.f, 0.f);
        for (int idx = t; idx < SMEM_FLOATS / 4; idx += BDIM) s4[idx] = z4;
    }
    __syncthreads();

    // Prologue: rows h0-1 (zeros if OOB), h0, h0+1, h0+2
    if (h0 > 0) load_row(smem, x, n, h0 - 1, cbase, t);
    load_row(smem, x, n, h0,     cbase, t);
    load_row(smem, x, n, h0 + 1, cbase, t);
    load_row(smem, x, n, h0 + 2, cbase, t);
    __syncthreads();

    const ulonglong2* wb = g_wb + (cbase >> 1) + ps;   // tap k at wb[k*128]
    const size_t gco = (size_t)gl * 9 * ROWW + cb;     // group band + col base

    float lsA = 0.f, lqA = 0.f, lsB = 0.f, lqB = 0.f;

    #pragma unroll 1
    for (int s = 0; s < 4; s++) {
        const int hr = h0 + 2 * s + rowteam;

        // Load the next two rows into free ring slots (write set 2s+3, 2s+4
        // disjoint from read set 2s-1..2s+2 mod 6; one barrier per step).
        if (s < 3) {
            load_row(smem, x, n, h0 + 2 * s + 3, cbase, t);
            const int r2 = h0 + 2 * s + 4;
            if (r2 < H_) load_row(smem, x, n, r2, cbase, t);
            else         zero_row(smem, r2, t);
        }

        const float* sl0 = smem + (size_t)slot_of(hr - 1) * SLOT + gco;
        const float* sl1 = smem + (size_t)slot_of(hr    ) * SLOT + gco;
        const float* sl2 = smem + (size_t)slot_of(hr + 1) * SLOT + gco;

        u64 MA[7], MB[7], mdA[8], mdB[8];
        #pragma unroll
        for (int q = 0; q < 7; q++) { MA[q] = 0ULL; MB[q] = 0ULL; }
        #pragma unroll
        for (int k = 0; k < 8; k++) { mdA[k] = 0ULL; mdB[k] = 0ULL; }

        #pragma unroll
        for (int dh = 0; dh < 3; dh++) {
            const float* slr = (dh == 0) ? sl0 : (dh == 1) ? sl1 : sl2;
            #pragma unroll
            for (int ii = 0; ii < 8; ii++) {
                const float* rowp = slr + ii * ROWW;
                // 9 aligned pairs PR[q] = (x[cb+2q-1], x[cb+2q]), LDS.64 each
                u64 PR[9];
                #pragma unroll
                for (int q = 0; q < 9; q++)
                    PR[q] = *(const u64*)(rowp + 2 * q);

                const ulonglong2 w0 = __ldg(&wb[(dh * 24 +      ii) * 128]);
                const ulonglong2 w1 = __ldg(&wb[(dh * 24 +  8 + ii) * 128]);
                const ulonglong2 w2 = __ldg(&wb[(dh * 24 + 16 + ii) * 128]);

                #pragma unroll
                for (int q = 0; q < 7; q++) {
                    MA[q] = fma2(PR[q],     w0.x, MA[q]);   // kw=0
                    MA[q] = fma2(PR[q + 1], w2.x, MA[q]);   // kw=2
                    MB[q] = fma2(PR[q],     w0.y, MB[q]);
                    MB[q] = fma2(PR[q + 1], w2.y, MB[q]);
                }
                #pragma unroll
                for (int k = 0; k < 8; k++) {               // kw=1 (shifted)
                    mdA[k] = fma2(PR[k], w1.x, mdA[k]);
                    mdB[k] = fma2(PR[k], w1.y, mdB[k]);
                }
            }
        }

        // Recombine main + shifted-mid, store coalesced float2, track stats.
        // out[2q]   = M[q].lo + mid[q].hi ; out[2q+1] = M[q].hi + mid[q+1].lo
        // (mid[0].lo belongs to out[cb-1], mid[7].hi to out[cb+14]: both are
        //  computed by the neighbouring team; discarded here.)
        float* yrow = y + ((size_t)(n * H_ + hr) * W_) * C_ + o0;
        #pragma unroll
        for (int q = 0; q < 7; q++) {
            const float vA0 = u2lo(MA[q]) + u2hi(mdA[q]);
            const float vA1 = u2hi(MA[q]) + u2lo(mdA[q + 1]);
            const float vB0 = u2lo(MB[q]) + u2hi(mdB[q]);
            const float vB1 = u2hi(MB[q]) + u2lo(mdB[q + 1]);
            *(float2*)(yrow + (size_t)(cb + 2 * q    ) * C_) = make_float2(vA0, vB0);
            *(float2*)(yrow + (size_t)(cb + 2 * q + 1) * C_) = make_float2(vA1, vB1);
            lsA += vA0 + vA1;  lqA += vA0 * vA0 + vA1 * vA1;
            lsB += vB0 + vB1;  lqB += vB0 * vB0 + vB1 * vB1;
        }

        __syncthreads();   // publishes loaded rows, retires window reads
    }

    const int pidx = (((bx * 32 + n) * 4) + team) * 2 + rowteam;
    g_psum  [(size_t)(o0    ) * NPART + pidx] = lsA;
    g_psumsq[(size_t)(o0    ) * NPART + pidx] = lqA;
    g_psum  [(size_t)(o0 + 1) * NPART + pidx] = lsB;
    g_psumsq[(size_t)(o0 + 1) * NPART + pidx] = lqB;
}

// ---------------------------------------------------------------------------
// Kernel 2: stats finalize — one block per channel
// ---------------------------------------------------------------------------
__global__ void stats_kernel(const float* __restrict__ gamma,
                             const float* __restrict__ beta)
{
    __shared__ float ss[128], sq[128];
    const int o = blockIdx.x;
    const int t = threadIdx.x;

    float s = 0.f, q = 0.f;
    const float* ps = g_psum   + (size_t)o * NPART;
    const float* pq = g_psumsq + (size_t)o * NPART;
    #pragma unroll
    for (int i = t; i < NPART; i += 128) { s += ps[i]; q += pq[i]; }
    ss[t] = s; sq[t] = q;
    __syncthreads();
    #pragma unroll
    for (int st = 64; st > 0; st >>= 1) {
        if (t < st) { ss[t] += ss[t + st]; sq[t] += sq[t + st]; }
        __syncthreads();
    }
    if (t == 0) {
        const float Ninv = 1.0f / (float)(B_ * H_ * W_);
        const float mean = ss[0] * Ninv;
        const float var  = sq[0] * Ninv - mean * mean;
        const float sc   = gamma[o] * rsqrtf(var + 1e-5f);
        g_scale[o] = sc;
        g_shift[o] = beta[o] - mean * sc;
    }
}

// ---------------------------------------------------------------------------
// Kernel 3: in-place normalize + ReLU (float4)
// ---------------------------------------------------------------------------
__global__ void norm_kernel(float* __restrict__ y, int n4)
{
    const int idx = blockIdx.x * blockDim.x + threadIdx.x;
    if (idx >= n4) return;
    float4 v = ((float4*)y)[idx];
    const int c = (idx * 4) & (C_ - 1);
    v.x = fmaxf(v.x * g_scale[c + 0] + g_shift[c + 0], 0.f);
    v.y = fmaxf(v.y * g_scale[c + 1] + g_shift[c + 1], 0.f);
    v.z = fmaxf(v.z * g_scale[c + 2] + g_shift[c + 2], 0.f);
    v.w = fmaxf(v.w * g_scale[c + 3] + g_shift[c + 3], 0.f);
    ((float4*)y)[idx] = v;
}

// ---------------------------------------------------------------------------
extern "C" void kernel_launch(void* const* d_in, const int* in_sizes, int n_in,
                              void* d_out, int out_size)
{
    const float* x     = (const float*)d_in[0];
    const float* w     = (const float*)d_in[1];
    // d_in[2] = bias: cancelled exactly by BatchNorm mean subtraction
    const float* gamma = (const float*)d_in[3];
    const float* beta  = (const float*)d_in[4];
    float* out = (float*)d_out;

    cudaFuncSetAttribute(conv_kernel,
                         cudaFuncAttributeMaxDynamicSharedMemorySize, SMEM_BYTES);

    wpack_kernel<<<36, 256>>>(w);                 // 72*128 entries

    dim3 grid(H_ / RPB, B_, 4);                   // (7, 32, 4)
    conv_kernel<<<grid, BDIM, SMEM_BYTES>>>(x, out);

    stats_kernel<<<C_, 128>>>(gamma, beta);

    const int n4 = out_size / 4;
    norm_kernel<<<(n4 + 255) / 256, 256>>>(out, n4);
}

// round 9
// speedup vs baseline: 1.7101x; 1.7101x over previous
#include <cuda_runtime.h>

// Problem constants
#define B_   32
#define H_   56
#define W_   56
#define C_   256

// Conv tiling: 64 channels/block, 2 rowteams x 4 col-teams x 32 channel-pairs
#define BDIM   256
#define CQTR   64        // channels per block
#define NGRP   8         // groups per block
#define ROWW   60        // padded smem row length (56 + halo + align, mult of 4)
#define CHPAD  (NGRP * 9)                    // 72, stride-9 padding
#define SLOT   (CHPAD * ROWW)                // 4320 floats per row-slot
#define NSLOT  6                             // ring: reads r-1..r+2, writes r+3,r+4
#define SMEM_FLOATS (NSLOT * SLOT)           // 25920
#define SMEM_BYTES  (SMEM_FLOATS * 4)        // 103680 -> 2 blocks/SM
#define RPB    8         // output rows per block (2 rows x 4 steps)

#define NPART  1792      // 7 rowblocks * 32 n * 4 teams * 2 rowteams

__device__ float g_psum  [C_ * NPART];
__device__ float g_psumsq[C_ * NPART];
__device__ float4 g_scale4[C_ / 4];          // 16B-aligned scale/shift
__device__ float4 g_shift4[C_ / 4];

typedef unsigned long long u64;

__device__ __forceinline__ u64 pack2(float lo, float hi) {
    u64 r; asm("mov.b64 %0, {%1, %2};" : "=l"(r) : "f"(lo), "f"(hi)); return r;
}
__device__ __forceinline__ u64 fma2(u64 a, u64 b, u64 c) {
    u64 d; asm("fma.rn.f32x2 %0, %1, %2, %3;" : "=l"(d) : "l"(a), "l"(b), "l"(c)); return d;
}
__device__ __forceinline__ float u2lo(u64 v) { return __uint_as_float((unsigned)v); }
__device__ __forceinline__ float u2hi(u64 v) { return __uint_as_float((unsigned)(v >> 32)); }

__device__ __forceinline__ int slot_of(int row) { return (row + 6) % 6; }

// LDG.128 -> 4x STS.32 load of one input row into its ring slot.
__device__ __forceinline__ void load_row(float* smem, const float* __restrict__ x,
                                         int n, int hh, int cbase, int t)
{
    float* slot = smem + (size_t)slot_of(hh) * SLOT;
    const float4* src = (const float4*)(x + ((size_t)(n * H_ + hh) * W_) * C_ + cbase);
    #pragma unroll
    for (int it = 0; it < 4; it++) {
        const int f = t + it * BDIM;
        if (f < 56 * 16) {
            const int col = f >> 4;
            const int c4  = f & 15;
            const float4 v = __ldg(&src[col * (C_ / 4) + c4]);
            const int g    = c4 >> 1;
            const int ioff = (c4 & 1) * 4;
            float* dst = slot + (size_t)(g * 9 + ioff) * ROWW + (col + 1);
            dst[0 * ROWW] = v.x;  dst[1 * ROWW] = v.y;
            dst[2 * ROWW] = v.z;  dst[3 * ROWW] = v.w;
        }
    }
}

__device__ __forceinline__ void zero_row(float* smem, int hh, int t)
{
    float* slot = smem + (size_t)slot_of(hh) * SLOT;
    #pragma unroll
    for (int it = 0; it < 4; it++) {
        const int f = t + it * BDIM;
        if (f < 56 * 16) {
            const int col = f >> 4;
            const int c4  = f & 15;
            const int g    = c4 >> 1;
            const int ioff = (c4 & 1) * 4;
            float* dst = slot + (size_t)(g * 9 + ioff) * ROWW + (col + 1);
            dst[0 * ROWW] = 0.f;  dst[1 * ROWW] = 0.f;
            dst[2 * ROWW] = 0.f;  dst[3 * ROWW] = 0.f;
        }
    }
}

// ---------------------------------------------------------------------------
// Kernel 1: grouped conv. Per thread: channel pair (A,B) x 14 cols, f32x2
// math with shifted-mid accumulators (no misalignment packs). Weights are
// small float2 LDGs from w (576 B/block -> L1-resident), packed in-register.
// 6-slot ring, one barrier per step. grid = (7, 32, 4); block = 256.
// Bias omitted (cancelled exactly by BN mean subtraction).
// ---------------------------------------------------------------------------
__global__ __launch_bounds__(BDIM, 2)
void conv_kernel(const float* __restrict__ x, const float* __restrict__ w,
                 float* __restrict__ y)
{
    extern __shared__ float smem[];
    const int t       = threadIdx.x;
    const int rowteam = t >> 7;            // 0/1
    const int tt      = t & 127;
    const int team    = tt >> 5;           // col team 0..3
    const int ps      = tt & 31;           // channel-pair slot
    const int gl      = ps >> 2;           // local group 0..7
    const int bx      = blockIdx.x;        // 0..6
    const int n       = blockIdx.y;
    const int z       = blockIdx.z;        // 0..3
    const int cbase   = z * CQTR;
    const int o0      = cbase + 2 * ps;    // first of channel pair (even)
    const int h0      = bx * RPB;
    const int cb      = team * 14;         // first output col (even)

    // Zero smem ring (halo cols + virtual OOB rows)
    {
        float4* s4 = (float4*)smem;
        const float4 z4 = make_float4(0.f, 0.f, 0.f, 0.f);
        for (int idx = t; idx < SMEM_FLOATS / 4; idx += BDIM) s4[idx] = z4;
    }
    __syncthreads();

    // Prologue: rows h0-1 (zeros if OOB), h0, h0+1, h0+2
    if (h0 > 0) load_row(smem, x, n, h0 - 1, cbase, t);
    load_row(smem, x, n, h0,     cbase, t);
    load_row(smem, x, n, h0 + 1, cbase, t);
    load_row(smem, x, n, h0 + 2, cbase, t);
    __syncthreads();

    const size_t gco = (size_t)gl * 9 * ROWW + cb;     // group band + col base
    float lsA = 0.f, lqA = 0.f, lsB = 0.f, lqB = 0.f;

    #pragma unroll 1
    for (int s = 0; s < 4; s++) {
        const int hr = h0 + 2 * s + rowteam;

        // Load next two rows into free ring slots (disjoint mod 6 from the
        // read window); single barrier per step at the bottom.
        if (s < 3) {
            load_row(smem, x, n, h0 + 2 * s + 3, cbase, t);
            const int r2 = h0 + 2 * s + 4;
            if (r2 < H_) load_row(smem, x, n, r2, cbase, t);
            else         zero_row(smem, r2, t);
        }

        const float* sl0 = smem + (size_t)slot_of(hr - 1) * SLOT + gco;
        const float* sl1 = smem + (size_t)slot_of(hr    ) * SLOT + gco;
        const float* sl2 = smem + (size_t)slot_of(hr + 1) * SLOT + gco;

        u64 MA[7], MB[7], mdA[8], mdB[8];
        #pragma unroll
        for (int q = 0; q < 7; q++) { MA[q] = 0ULL; MB[q] = 0ULL; }
        #pragma unroll
        for (int k = 0; k < 8; k++) { mdA[k] = 0ULL; mdB[k] = 0ULL; }

        #pragma unroll
        for (int dh = 0; dh < 3; dh++) {
            const float* slr = (dh == 0) ? sl0 : (dh == 1) ? sl1 : sl2;
            #pragma unroll
            for (int ii = 0; ii < 8; ii++) {
                const float* rowp = slr + ii * ROWW;
                // 9 aligned input pairs PR[q] = (x[cb+2q-1], x[cb+2q])
                u64 PR[9];
                #pragma unroll
                for (int q = 0; q < 9; q++)
                    PR[q] = *(const u64*)(rowp + 2 * q);

                // 3 taps for this (dh, ii), channel pair: L1-resident LDG.64
                const float2 t0 = __ldg((const float2*)&w[(dh * 24 +      ii) * C_ + o0]);
                const float2 t1 = __ldg((const float2*)&w[(dh * 24 +  8 + ii) * C_ + o0]);
                const float2 t2 = __ldg((const float2*)&w[(dh * 24 + 16 + ii) * C_ + o0]);
                const u64 WA0 = pack2(t0.x, t0.x), WB0 = pack2(t0.y, t0.y);
                const u64 WA1 = pack2(t1.x, t1.x), WB1 = pack2(t1.y, t1.y);
                const u64 WA2 = pack2(t2.x, t2.x), WB2 = pack2(t2.y, t2.y);

                #pragma unroll
                for (int q = 0; q < 7; q++) {
                    MA[q] = fma2(PR[q],     WA0, MA[q]);   // kw=0
                    MA[q] = fma2(PR[q + 1], WA2, MA[q]);   // kw=2
                    MB[q] = fma2(PR[q],     WB0, MB[q]);
                    MB[q] = fma2(PR[q + 1], WB2, MB[q]);
                }
                #pragma unroll
                for (int k = 0; k < 8; k++) {              // kw=1 (shifted)
                    mdA[k] = fma2(PR[k], WA1, mdA[k]);
                    mdB[k] = fma2(PR[k], WB1, mdB[k]);
                }
            }
        }

        // Recombine main + shifted-mid, store coalesced float2, track stats.
        // out[2q]   = M[q].lo + mid[q].hi ; out[2q+1] = M[q].hi + mid[q+1].lo
        float* yrow = y + ((size_t)(n * H_ + hr) * W_) * C_ + o0;
        #pragma unroll
        for (int q = 0; q < 7; q++) {
            const float vA0 = u2lo(MA[q]) + u2hi(mdA[q]);
            const float vA1 = u2hi(MA[q]) + u2lo(mdA[q + 1]);
            const float vB0 = u2lo(MB[q]) + u2hi(mdB[q]);
            const float vB1 = u2hi(MB[q]) + u2lo(mdB[q + 1]);
            *(float2*)(yrow + (size_t)(cb + 2 * q    ) * C_) = make_float2(vA0, vB0);
            *(float2*)(yrow + (size_t)(cb + 2 * q + 1) * C_) = make_float2(vA1, vB1);
            lsA += vA0 + vA1;  lqA += vA0 * vA0 + vA1 * vA1;
            lsB += vB0 + vB1;  lqB += vB0 * vB0 + vB1 * vB1;
        }

        __syncthreads();   // publishes loaded rows, retires window reads
    }

    const int pidx = (((bx * 32 + n) * 4) + team) * 2 + rowteam;
    g_psum  [(size_t)(o0    ) * NPART + pidx] = lsA;
    g_psumsq[(size_t)(o0    ) * NPART + pidx] = lqA;
    g_psum  [(size_t)(o0 + 1) * NPART + pidx] = lsB;
    g_psumsq[(size_t)(o0 + 1) * NPART + pidx] = lqB;
}

// ---------------------------------------------------------------------------
// Kernel 2: stats finalize — one block per channel
// ---------------------------------------------------------------------------
__global__ void stats_kernel(const float* __restrict__ gamma,
                             const float* __restrict__ beta)
{
    __shared__ float ss[128], sq[128];
    const int o = blockIdx.x;
    const int t = threadIdx.x;

    float s = 0.f, q = 0.f;
    const float* ps = g_psum   + (size_t)o * NPART;
    const float* pq = g_psumsq + (size_t)o * NPART;
    #pragma unroll
    for (int i = t; i < NPART; i += 128) { s += ps[i]; q += pq[i]; }
    ss[t] = s; sq[t] = q;
    __syncthreads();
    #pragma unroll
    for (int st = 64; st > 0; st >>= 1) {
        if (t < st) { ss[t] += ss[t + st]; sq[t] += sq[t + st]; }
        __syncthreads();
    }
    if (t == 0) {
        const float Ninv = 1.0f / (float)(B_ * H_ * W_);
        const float mean = ss[0] * Ninv;
        const float var  = sq[0] * Ninv - mean * mean;
        const float sc   = gamma[o] * rsqrtf(var + 1e-5f);
        ((float*)g_scale4)[o] = sc;
        ((float*)g_shift4)[o] = beta[o] - mean * sc;
    }
}

// ---------------------------------------------------------------------------
// Kernel 3: in-place normalize + ReLU. Grid-stride with stride % 64 == 0
// (in float4 units) so each thread's channel quartet is INVARIANT: scale and
// shift are loaded exactly once per thread -> pure DRAM-bound stream.
// ---------------------------------------------------------------------------
#define NORM_BLOCKS 1184   // stride = 1184*256 float4s, multiple of 64

__global__ void norm_kernel(float* __restrict__ y, int n4)
{
    const int tid0   = blockIdx.x * blockDim.x + threadIdx.x;
    const int stride = gridDim.x * blockDim.x;
    const int c4     = tid0 & 63;              // float4-channel index, invariant

    const float4 sc = __ldg(&g_scale4[c4]);
    const float4 sh = __ldg(&g_shift4[c4]);

    float4* y4 = (float4*)y;
    for (int idx = tid0; idx < n4; idx += stride) {
        float4 v = y4[idx];
        v.x = fmaxf(fmaf(v.x, sc.x, sh.x), 0.f);
        v.y = fmaxf(fmaf(v.y, sc.y, sh.y), 0.f);
        v.z = fmaxf(fmaf(v.z, sc.z, sh.z), 0.f);
        v.w = fmaxf(fmaf(v.w, sc.w, sh.w), 0.f);
        y4[idx] = v;
    }
}

// ---------------------------------------------------------------------------
extern "C" void kernel_launch(void* const* d_in, const int* in_sizes, int n_in,
                              void* d_out, int out_size)
{
    const float* x     = (const float*)d_in[0];
    const float* w     = (const float*)d_in[1];
    // d_in[2] = bias: cancelled exactly by BatchNorm mean subtraction
    const float* gamma = (const float*)d_in[3];
    const float* beta  = (const float*)d_in[4];
    float* out = (float*)d_out;

    cudaFuncSetAttribute(conv_kernel,
                         cudaFuncAttributeMaxDynamicSharedMemorySize, SMEM_BYTES);

    dim3 grid(H_ / RPB, B_, 4);                   // (7, 32, 4)
    conv_kernel<<<grid, BDIM, SMEM_BYTES>>>(x, w, out);

    stats_kernel<<<C_, 128>>>(gamma, beta);

    const int n4 = out_size / 4;
    norm_kernel<<<NORM_BLOCKS, 256>>>(out, n4);
}